// round 9
// baseline (speedup 1.0000x reference)
#include <cuda_runtime.h>
#include <cuda_bf16.h>
#include <cstdint>
#include <math.h>

// Problem constants
#define S_LEN 4096
#define D_MODEL 512
#define SLOPE 0.5f
#define QT 32
#define NKEY 128
#define WBACK 96
#define NB 4

// Scratch
__device__ float g_Q[NB * S_LEN * D_MODEL];     // tf32-rounded floats
__device__ float g_V[NB * S_LEN * D_MODEL];     // tf32-rounded floats (bias added)
__device__ uint32_t g_Xt[NB * S_LEN * D_MODEL]; // X pre-rounded to tf32
__device__ uint32_t g_Wt[1024 * 512];           // [Wqk | Wv^T] tf32, [n][k]

// ---------------------------------------------------------------------------
// Helpers
// ---------------------------------------------------------------------------
__device__ __forceinline__ void mma16808(float* d, const uint32_t* a,
                                         uint32_t b0, uint32_t b1)
{
    asm volatile(
        "mma.sync.aligned.m16n8k8.row.col.f32.tf32.tf32.f32 "
        "{%0,%1,%2,%3}, {%4,%5,%6,%7}, {%8,%9}, {%0,%1,%2,%3};"
        : "+f"(d[0]), "+f"(d[1]), "+f"(d[2]), "+f"(d[3])
        : "r"(a[0]), "r"(a[1]), "r"(a[2]), "r"(a[3]), "r"(b0), "r"(b1));
}

__device__ __forceinline__ uint32_t f2tf32(float x) {
    uint32_t t;
    asm("cvt.rna.tf32.f32 %0, %1;" : "=r"(t) : "f"(x));
    return t;
}

__device__ __forceinline__ void cpa16(uint32_t dst, const void* src) {
    asm volatile("cp.async.cg.shared.global [%0], [%1], 16;"
                 :: "r"(dst), "l"(src) : "memory");
}
__device__ __forceinline__ void sts_zero16(uint32_t dst) {
    asm volatile("st.shared.v4.b32 [%0], {%1,%1,%1,%1};" :: "r"(dst), "r"(0u)
                 : "memory");
}
#define CPA_COMMIT() asm volatile("cp.async.commit_group;" ::: "memory")
#define CPA_WAIT0()  asm volatile("cp.async.wait_group 0;" ::: "memory")

// ---------------------------------------------------------------------------
// pack_all: X -> tf32 (g_Xt), [Wqk | Wv^T] -> tf32 (g_Wt)
// ---------------------------------------------------------------------------
__global__ void pack_all(const float* __restrict__ X,
                         const float* __restrict__ Wqk,
                         const float* __restrict__ Wv)
{
    int bid = blockIdx.x;
    if (bid < 8192) {
        int idx = bid * 256 + threadIdx.x;       // float4 over X (2,097,152)
        float4 v = reinterpret_cast<const float4*>(X)[idx];
        uint4 t;
        t.x = f2tf32(v.x); t.y = f2tf32(v.y);
        t.z = f2tf32(v.z); t.w = f2tf32(v.w);
        reinterpret_cast<uint4*>(g_Xt)[idx] = t;
    } else {
        int idx = (bid - 8192) * 256 + threadIdx.x;   // 0..524287
        int n = idx >> 9, k = idx & 511;
        float w = (n < 512) ? Wqk[k * 512 + n] : Wv[(n - 512) * 512 + k];
        g_Wt[idx] = f2tf32(w);
    }
}

// ---------------------------------------------------------------------------
// tf32 mma GEMM: [Q|V][16384, 1024] = Xt[16384,512] @ W^T
// Outputs stored tf32-rounded (consumed only by tf32 attention).
// ---------------------------------------------------------------------------
#define STRF 68
#define APLANE (128 * STRF)

__global__ __launch_bounds__(256)
void mma_gemm(const float* __restrict__ bias,
              float* __restrict__ Q, float* __restrict__ V)
{
    extern __shared__ uint32_t smw[];
    uint32_t* sA = smw;
    uint32_t* sB = smw + APLANE;

    const int tid = threadIdx.x;
    const int wid = tid >> 5;
    const int lane = tid & 31;
    const int g = lane >> 2;
    const int t4 = lane & 3;
    const int warp_m = wid & 3;
    const int warp_n = wid >> 2;
    const int m0 = blockIdx.x * 128;
    const int n0 = blockIdx.y * 128;

    float acc[2][8][4];
#pragma unroll
    for (int mt = 0; mt < 2; mt++)
#pragma unroll
        for (int nt = 0; nt < 8; nt++)
#pragma unroll
            for (int i = 0; i < 4; i++) acc[mt][nt][i] = 0.f;

    const int lrow = tid >> 4;
    const int lc4  = (tid & 15) << 2;

    for (int c = 0; c < 8; c++) {
        const int k0 = c * 64;
        uint4 av[8], bv[8];
#pragma unroll
        for (int i = 0; i < 8; i++) {
            int row = lrow + 16 * i;
            av[i] = *reinterpret_cast<const uint4*>(
                &g_Xt[(size_t)(m0 + row) * 512 + k0 + lc4]);
            bv[i] = *reinterpret_cast<const uint4*>(
                &g_Wt[(size_t)(n0 + row) * 512 + k0 + lc4]);
        }
        if (c) __syncthreads();
#pragma unroll
        for (int i = 0; i < 8; i++) {
            int row = lrow + 16 * i;
            *reinterpret_cast<uint4*>(&sA[row * STRF + lc4]) = av[i];
            *reinterpret_cast<uint4*>(&sB[row * STRF + lc4]) = bv[i];
        }
        __syncthreads();
#pragma unroll
        for (int k8 = 0; k8 < 8; k8++) {
            const int kc = k8 * 8 + t4;
            uint32_t a[2][4];
#pragma unroll
            for (int mt = 0; mt < 2; mt++) {
                int r = warp_m * 32 + mt * 16 + g;
                a[mt][0] = sA[r * STRF + kc];
                a[mt][1] = sA[(r + 8) * STRF + kc];
                a[mt][2] = sA[r * STRF + kc + 4];
                a[mt][3] = sA[(r + 8) * STRF + kc + 4];
            }
#pragma unroll
            for (int nt = 0; nt < 8; nt++) {
                int rn = warp_n * 64 + nt * 8 + g;
                uint32_t b0 = sB[rn * STRF + kc];
                uint32_t b1 = sB[rn * STRF + kc + 4];
#pragma unroll
                for (int mt = 0; mt < 2; mt++)
                    mma16808(acc[mt][nt], a[mt], b0, b1);
            }
        }
    }

#pragma unroll
    for (int mt = 0; mt < 2; mt++) {
        int row0 = m0 + warp_m * 32 + mt * 16 + g;
#pragma unroll
        for (int nt = 0; nt < 8; nt++) {
            int col = n0 + warp_n * 64 + nt * 8 + t4 * 2;
            if (col < 512) {
                float2 lo = make_float2(
                    __uint_as_float(f2tf32(acc[mt][nt][0])),
                    __uint_as_float(f2tf32(acc[mt][nt][1])));
                float2 hi = make_float2(
                    __uint_as_float(f2tf32(acc[mt][nt][2])),
                    __uint_as_float(f2tf32(acc[mt][nt][3])));
                *reinterpret_cast<float2*>(&Q[(size_t)row0 * 512 + col]) = lo;
                *reinterpret_cast<float2*>(&Q[(size_t)(row0 + 8) * 512 + col]) = hi;
            } else {
                int vc = col - 512;
                float2 b2 = *reinterpret_cast<const float2*>(&bias[vc]);
                float2 lo = make_float2(
                    __uint_as_float(f2tf32(acc[mt][nt][0] + b2.x)),
                    __uint_as_float(f2tf32(acc[mt][nt][1] + b2.y)));
                float2 hi = make_float2(
                    __uint_as_float(f2tf32(acc[mt][nt][2] + b2.x)),
                    __uint_as_float(f2tf32(acc[mt][nt][3] + b2.y)));
                *reinterpret_cast<float2*>(&V[(size_t)row0 * 512 + vc]) = lo;
                *reinterpret_cast<float2*>(&V[(size_t)(row0 + 8) * 512 + vc]) = hi;
            }
        }
    }
}

// ---------------------------------------------------------------------------
// Tensor-core windowed attention, cp.async double-buffered.
// CTA = 32 queries x 128-key band, 8 warps.
// Smem (words): sP[32][132] @0; phase1 bufs Q0@4224,K0@6400,Q1@15104,K1@17280;
// phase3 V0@4224, V1@13440. Total 25984 words = 103936 B.
// ---------------------------------------------------------------------------
#define SP_STR 132
#define QK_STR 68
#define VC_STR 72
#define W_Q0 4224
#define W_K0 6400
#define W_Q1 15104
#define W_K1 17280
#define W_V0 4224
#define W_V1 13440
#define ATTN_W 25984

__global__ __launch_bounds__(256, 2)
void attn_tc(const float* __restrict__ Q, const float* __restrict__ V,
             float* __restrict__ O)
{
    extern __shared__ uint32_t smw[];
    float* sP = reinterpret_cast<float*>(smw);
    const uint32_t sbase = (uint32_t)__cvta_generic_to_shared(smw);

    const int tid = threadIdx.x;
    const int wid = tid >> 5;
    const int lane = tid & 31;
    const int g = lane >> 2;
    const int t4 = lane & 3;
    const int b  = blockIdx.y;
    const int i0 = blockIdx.x * QT;
    const int jstart = i0 - WBACK;

    const float* Qb = Q + (size_t)b * S_LEN * D_MODEL;
    const float* Vb = V + (size_t)b * S_LEN * D_MODEL;
    const uint32_t* Kb = g_Xt + (size_t)b * S_LEN * D_MODEL;

    const int wm = wid & 1;
    const int wn = wid >> 1;      // 0..3

    // loader lambdas (as macros via inline code)
    const int l_row_q = (tid >> 4);            // reused for Q (idx<512) & K
    const int l_c4 = (tid & 15) << 2;

    // ---- phase 1 prologue: chunk 0 ----
    {
        const int k0 = 0;
#pragma unroll
        for (int i = 0; i < 2; i++) {
            int idx = tid + 256 * i;
            int row = idx >> 4, c4 = (idx & 15) << 2;
            cpa16(sbase + (W_Q0 + row * QK_STR + c4) * 4,
                  &Qb[(size_t)(i0 + row) * 512 + k0 + c4]);
        }
#pragma unroll
        for (int i = 0; i < 8; i++) {
            int idx = tid + 256 * i;
            int row = idx >> 4, c4 = (idx & 15) << 2;
            int j = jstart + row;
            uint32_t dst = sbase + (W_K0 + row * QK_STR + c4) * 4;
            if (j >= 0) cpa16(dst, &Kb[(size_t)j * 512 + k0 + c4]);
            else sts_zero16(dst);
        }
        CPA_COMMIT();
    }

    float accs[4][4];
#pragma unroll
    for (int nt = 0; nt < 4; nt++)
#pragma unroll
        for (int i = 0; i < 4; i++) accs[nt][i] = 0.f;

    for (int c = 0; c < 8; c++) {
        CPA_WAIT0();
        __syncthreads();
        if (c < 7) {
            const int k0 = (c + 1) * 64;
            const int wq = ((c + 1) & 1) ? W_Q1 : W_Q0;
            const int wk = ((c + 1) & 1) ? W_K1 : W_K0;
#pragma unroll
            for (int i = 0; i < 2; i++) {
                int idx = tid + 256 * i;
                int row = idx >> 4, c4 = (idx & 15) << 2;
                cpa16(sbase + (wq + row * QK_STR + c4) * 4,
                      &Qb[(size_t)(i0 + row) * 512 + k0 + c4]);
            }
#pragma unroll
            for (int i = 0; i < 8; i++) {
                int idx = tid + 256 * i;
                int row = idx >> 4, c4 = (idx & 15) << 2;
                int j = jstart + row;
                uint32_t dst = sbase + (wk + row * QK_STR + c4) * 4;
                if (j >= 0) cpa16(dst, &Kb[(size_t)j * 512 + k0 + c4]);
                else sts_zero16(dst);
            }
            CPA_COMMIT();
        }
        const uint32_t* sQ = smw + ((c & 1) ? W_Q1 : W_Q0);
        const uint32_t* sK = smw + ((c & 1) ? W_K1 : W_K0);
#pragma unroll
        for (int k8 = 0; k8 < 8; k8++) {
            const int kc = k8 * 8 + t4;
            uint32_t a[4];
            int r = wm * 16 + g;
            a[0] = sQ[r * QK_STR + kc];
            a[1] = sQ[(r + 8) * QK_STR + kc];
            a[2] = sQ[r * QK_STR + kc + 4];
            a[3] = sQ[(r + 8) * QK_STR + kc + 4];
#pragma unroll
            for (int nt = 0; nt < 4; nt++) {
                int rn = wn * 32 + nt * 8 + g;
                uint32_t b0 = sK[rn * QK_STR + kc];
                uint32_t b1 = sK[rn * QK_STR + kc + 4];
                mma16808(accs[nt], a, b0, b1);
            }
        }
    }

    // scale + ALiBi + causal mask -> sP
    const float scale = 0.04419417382415922f;
#pragma unroll
    for (int nt = 0; nt < 4; nt++) {
#pragma unroll
        for (int h = 0; h < 2; h++) {
            int row = wm * 16 + g + 8 * h;
            int i = i0 + row;
#pragma unroll
            for (int cp = 0; cp < 2; cp++) {
                int col = wn * 32 + nt * 8 + t4 * 2 + cp;
                int j = jstart + col;
                float v = accs[nt][h * 2 + cp];
                float s = (j < 0 || j > i) ? -1e30f
                        : v * scale + SLOPE * (float)(j - i);
                sP[row * SP_STR + col] = s;
            }
        }
    }
    __syncthreads();

    // ---- issue V chunk 0 (overlaps softmax) ----
    {
#pragma unroll
        for (int i = 0; i < 8; i++) {
            int idx = tid + 256 * i;
            int row = idx >> 4, c4 = (idx & 15) << 2;
            int j = jstart + row;
            uint32_t dst = sbase + (W_V0 + row * VC_STR + c4) * 4;
            if (j >= 0) cpa16(dst, &Vb[(size_t)j * 512 + 0 + c4]);
            else sts_zero16(dst);
        }
        CPA_COMMIT();
    }

    // ---- softmax ----
    {
        int r = tid >> 3;
        int l = tid & 7;
        float* row = &sP[r * SP_STR];
        float m = -1e30f;
#pragma unroll
        for (int k = 0; k < 16; k++) m = fmaxf(m, row[l * 16 + k]);
#pragma unroll
        for (int o = 4; o > 0; o >>= 1)
            m = fmaxf(m, __shfl_xor_sync(0xffffffffu, m, o));
        float sum = 0.f;
        float e[16];
#pragma unroll
        for (int k = 0; k < 16; k++) {
            e[k] = __expf(row[l * 16 + k] - m);
            sum += e[k];
        }
#pragma unroll
        for (int o = 4; o > 0; o >>= 1)
            sum += __shfl_xor_sync(0xffffffffu, sum, o);
        float inv = 1.f / sum;
#pragma unroll
        for (int k = 0; k < 16; k++)
            row[l * 16 + k] = __uint_as_float(f2tf32(e[k] * inv));
    }
    __syncthreads();

    // ---- P fragments -> registers (reused for all 8 output chunks) ----
    const uint32_t* sPu = reinterpret_cast<const uint32_t*>(sP);
    uint32_t pa[16][4];
    {
        int r = wm * 16 + g;
#pragma unroll
        for (int k8 = 0; k8 < 16; k8++) {
            int kc = k8 * 8 + t4;
            pa[k8][0] = sPu[r * SP_STR + kc];
            pa[k8][1] = sPu[(r + 8) * SP_STR + kc];
            pa[k8][2] = sPu[r * SP_STR + kc + 4];
            pa[k8][3] = sPu[(r + 8) * SP_STR + kc + 4];
        }
    }

    // ---- phase 3: O = P @ V, 64-feature chunks ----
    const int wn8 = wid >> 1;
    for (int ch = 0; ch < 8; ch++) {
        CPA_WAIT0();
        __syncthreads();
        if (ch < 7) {
            const int e0 = (ch + 1) * 64;
            const int wv = ((ch + 1) & 1) ? W_V1 : W_V0;
#pragma unroll
            for (int i = 0; i < 8; i++) {
                int idx = tid + 256 * i;
                int row = idx >> 4, c4 = (idx & 15) << 2;
                int j = jstart + row;
                uint32_t dst = sbase + (wv + row * VC_STR + c4) * 4;
                if (j >= 0) cpa16(dst, &Vb[(size_t)j * 512 + e0 + c4]);
                else sts_zero16(dst);
            }
            CPA_COMMIT();
        }
        const uint32_t* sV = smw + ((ch & 1) ? W_V1 : W_V0);

        float acco[2][4];
#pragma unroll
        for (int nt = 0; nt < 2; nt++)
#pragma unroll
            for (int i = 0; i < 4; i++) acco[nt][i] = 0.f;

#pragma unroll
        for (int k8 = 0; k8 < 16; k8++) {
            const int kr = k8 * 8 + t4;
#pragma unroll
            for (int nt = 0; nt < 2; nt++) {
                int nf = wn8 * 16 + nt * 8 + g;
                uint32_t b0 = sV[kr * VC_STR + nf];
                uint32_t b1 = sV[(kr + 4) * VC_STR + nf];
                mma16808(acco[nt], pa[k8], b0, b1);
            }
        }

        const int e0 = ch * 64;
#pragma unroll
        for (int nt = 0; nt < 2; nt++) {
            int col = e0 + wn8 * 16 + nt * 8 + t4 * 2;
            int row0 = i0 + wm * 16 + g;
            *reinterpret_cast<float2*>(
                &O[((size_t)b * S_LEN + row0) * 512 + col]) =
                make_float2(acco[nt][0], acco[nt][1]);
            *reinterpret_cast<float2*>(
                &O[((size_t)b * S_LEN + row0 + 8) * 512 + col]) =
                make_float2(acco[nt][2], acco[nt][3]);
        }
    }
}

// ---------------------------------------------------------------------------
extern "C" void kernel_launch(void* const* d_in, const int* in_sizes, int n_in,
                              void* d_out, int out_size)
{
    const float* x   = (const float*)d_in[0];
    const float* Wqk = (const float*)d_in[1];
    const float* Wv  = (const float*)d_in[2];
    const float* bv  = (const float*)d_in[3];
    float* out = (float*)d_out;

    float *Qp = nullptr, *Vp = nullptr;
    cudaGetSymbolAddress((void**)&Qp, g_Q);
    cudaGetSymbolAddress((void**)&Vp, g_V);

    const int gemm_smem = 2 * APLANE * 4;
    cudaFuncSetAttribute(mma_gemm, cudaFuncAttributeMaxDynamicSharedMemorySize,
                         gemm_smem);
    const int attn_smem = ATTN_W * 4;
    cudaFuncSetAttribute(attn_tc, cudaFuncAttributeMaxDynamicSharedMemorySize,
                         attn_smem);

    pack_all<<<10240, 256>>>(x, Wqk, Wv);

    dim3 ggemm(128, 8);
    mma_gemm<<<ggemm, 256, gemm_smem>>>(bv, Qp, Vp);

    dim3 gattn(S_LEN / QT, NB);
    attn_tc<<<gattn, 256, attn_smem>>>(Qp, Vp, out);
}